// round 4
// baseline (speedup 1.0000x reference)
#include <cuda_runtime.h>

// ---------------------------------------------------------------------------
// EncoderBiLSTMMaxPool: 2-layer bidirectional LSTM, hidden carried across
// samples, reset every 32 samples -> 4 independent chains x 2 dirs.
//
//   1. embed:  emb = E_rt[rt] + E_re[re] + E_rm[rm]          (16384 x 512)
//   2. gemm:   gx  = input @ Wih[l]^T + (bih+bhh)            (16384 x 2048)
//              FFMA2 (f32x2) inner loop
//   3. lstm:   recurrence, 8 clusters of 8 CTAs, warp-shuffle gate combine,
//              st.async + tx-counting mbarriers (no __syncthreads in loop)
//   4. repeat 2,3 for layer 1 (into d_out)
//   5. maxpool over batch axis -> (S, H)
// ---------------------------------------------------------------------------

#define Bn   128
#define Sn   128
#define Hn   512
#define HHn  256
#define NROW 16384
#define GXN  2048

typedef unsigned long long ull;

__device__ float g_emb[NROW * Hn];
__device__ float g_x  [NROW * GXN];
__device__ float g_y0 [NROW * Hn];

// ---------------------------------------------------------------------------
// helpers
// ---------------------------------------------------------------------------
__device__ __forceinline__ unsigned smem_u32(const void* p) {
    return (unsigned)__cvta_generic_to_shared(p);
}
__device__ __forceinline__ unsigned mapa_cluster(unsigned addr, unsigned rank) {
    unsigned r;
    asm volatile("mapa.shared::cluster.u32 %0, %1, %2;" : "=r"(r) : "r"(addr), "r"(rank));
    return r;
}
__device__ __forceinline__ void cluster_sync_() {
    asm volatile("barrier.cluster.arrive.aligned;" ::: "memory");
    asm volatile("barrier.cluster.wait.aligned;" ::: "memory");
}
__device__ __forceinline__ void mbar_init(unsigned bar, unsigned cnt) {
    asm volatile("mbarrier.init.shared.b64 [%0], %1;" :: "r"(bar), "r"(cnt) : "memory");
}
__device__ __forceinline__ void mbar_arm(unsigned bar, unsigned tx) {
    asm volatile("mbarrier.arrive.expect_tx.shared::cta.b64 _, [%0], %1;"
                 :: "r"(bar), "r"(tx) : "memory");
}
__device__ __forceinline__ void mbar_wait(unsigned bar, unsigned parity) {
    asm volatile(
        "{\n\t.reg .pred P;\n"
        "LW%=:\n\t"
        "mbarrier.try_wait.parity.acquire.cta.shared::cta.b64 P, [%0], %1, 0x989680;\n\t"
        "@!P bra LW%=;\n\t}"
        :: "r"(bar), "r"(parity) : "memory");
}
__device__ __forceinline__ void st_async_f32(unsigned dst, float v, unsigned bar) {
    asm volatile("st.async.shared::cluster.mbarrier::complete_tx::bytes.b32 [%0], %1, [%2];"
                 :: "r"(dst), "r"(__float_as_uint(v)), "r"(bar) : "memory");
}
__device__ __forceinline__ float tanh_fast(float x) {
    float r;
    asm("tanh.approx.f32 %0, %1;" : "=f"(r) : "f"(x));
    return r;
}
__device__ __forceinline__ float sigmoid_fast(float x) {
    return fmaf(0.5f, tanh_fast(0.5f * x), 0.5f);
}
__device__ __forceinline__ void fma2(ull& acc, ull a, ull b) {
    asm("fma.rn.f32x2 %0, %1, %2, %0;" : "+l"(acc) : "l"(a), "l"(b));
}
__device__ __forceinline__ float sum2(ull a) {
    unsigned lo, hi;
    asm("mov.b64 {%0,%1}, %2;" : "=r"(lo), "=r"(hi) : "l"(a));
    return __uint_as_float(lo) + __uint_as_float(hi);
}

// ---------------------------------------------------------------------------
// 1) embedding sum
// ---------------------------------------------------------------------------
__global__ void embed_kernel(const int* __restrict__ rt, const int* __restrict__ re,
                             const int* __restrict__ rm,
                             const float* __restrict__ Ert, const float* __restrict__ Ere,
                             const float* __restrict__ Erm)
{
    int row = blockIdx.x;
    int t   = threadIdx.x;
    long irt = rt[row], ire = re[row], irm = rm[row];
    const float4* a = (const float4*)(Ert + irt * (long)Hn);
    const float4* b = (const float4*)(Ere + ire * (long)Hn);
    const float4* c = (const float4*)(Erm + irm * (long)Hn);
    float4 va = a[t], vb = b[t], vc = c[t];
    float4 o;
    o.x = va.x + vb.x + vc.x;
    o.y = va.y + vb.y + vc.y;
    o.z = va.z + vb.z + vc.z;
    o.w = va.w + vb.w + vc.w;
    ((float4*)(g_emb + (long)row * Hn))[t] = o;
}

// ---------------------------------------------------------------------------
// 2) fp32 GEMM with packed f32x2 FFMA.
//    C[m,n] = sum_k A[m,k]*W[n,k] + bih[n] + bhh[n]
//    M=16384, N=2048, K=512. BM=128, BN=64, BK=16, 256 thr.
//    Thread (tx 0..15, ty 0..15): m = bm+ty*8+{0..7} (as 4 f32x2 pairs),
//    n = bn + tx + 16j, j=0..3 (lane-interleaved -> conflict-free LDS.64).
//    W duplicated in smem as (w,w) pairs so one FFMA2 does 2 m-rows.
// ---------------------------------------------------------------------------
__global__ __launch_bounds__(256) void gemm_kernel(
    const float* __restrict__ A, const float* __restrict__ W,
    const float* __restrict__ bih, const float* __restrict__ bhh,
    float* __restrict__ C)
{
    __shared__ __align__(16) float  As [16][128];
    __shared__ __align__(16) float2 Ws2[16][66];   // 64 used + pad

    const int bm = blockIdx.y * 128;
    const int bn = blockIdx.x * 64;
    const int tid = threadIdx.x;
    const int tx = tid & 15;
    const int ty = tid >> 4;

    ull acc[4][4];
#pragma unroll
    for (int i = 0; i < 4; i++)
#pragma unroll
        for (int j = 0; j < 4; j++) acc[i][j] = 0ull;

    for (int k0 = 0; k0 < 512; k0 += 16) {
        // A tile: 128x16, transposed into As[k][m]
#pragma unroll
        for (int i = 0; i < 2; i++) {
            int f4 = tid * 2 + i;
            int r = f4 >> 2, c4 = f4 & 3;
            float4 v = *(const float4*)(A + (long)(bm + r) * 512 + k0 + c4 * 4);
            As[c4 * 4 + 0][r] = v.x;
            As[c4 * 4 + 1][r] = v.y;
            As[c4 * 4 + 2][r] = v.z;
            As[c4 * 4 + 3][r] = v.w;
        }
        // W tile: 64x16, duplicated pairs into Ws2[k][n]
        {
            int r = tid >> 2, c4 = tid & 3;
            float4 v = *(const float4*)(W + (long)(bn + r) * 512 + k0 + c4 * 4);
            Ws2[c4 * 4 + 0][r] = make_float2(v.x, v.x);
            Ws2[c4 * 4 + 1][r] = make_float2(v.y, v.y);
            Ws2[c4 * 4 + 2][r] = make_float2(v.z, v.z);
            Ws2[c4 * 4 + 3][r] = make_float2(v.w, v.w);
        }
        __syncthreads();
#pragma unroll
        for (int k = 0; k < 16; k++) {
            ull a2[4], w2[4];
#pragma unroll
            for (int i = 0; i < 4; i++)
                a2[i] = *(const ull*)&As[k][ty * 8 + 2 * i];
#pragma unroll
            for (int j = 0; j < 4; j++)
                w2[j] = *(const ull*)&Ws2[k][tx + 16 * j];
#pragma unroll
            for (int i = 0; i < 4; i++)
#pragma unroll
                for (int j = 0; j < 4; j++)
                    fma2(acc[i][j], a2[i], w2[j]);
        }
        __syncthreads();
    }

#pragma unroll
    for (int j = 0; j < 4; j++) {
        int n = bn + tx + 16 * j;
        float bias = bih[n] + bhh[n];
#pragma unroll
        for (int i = 0; i < 4; i++) {
            unsigned lo, hi;
            asm("mov.b64 {%0,%1}, %2;" : "=r"(lo), "=r"(hi) : "l"(acc[i][j]));
            int m0 = bm + ty * 8 + 2 * i;
            C[(long)m0 * GXN + n]       = __uint_as_float(lo) + bias;
            C[(long)(m0 + 1) * GXN + n] = __uint_as_float(hi) + bias;
        }
    }
}

// ---------------------------------------------------------------------------
// 3) LSTM recurrence. 8 clusters of 8 CTAs, 256 threads/CTA (8 warps).
//    Lane layout inside a warp (32 lanes = 4 units x 4 gates x 2 K-halves):
//       lane = ug*8 + gate*2 + half,  unit_local = warp*4 + ug
//    Per step: mbar wait -> FFMA2 half-dot -> shfl_xor half-sum -> +x
//    -> per-lane activation -> 4x shfl.idx gate gather -> c,h (redundant in
//    all 8 lanes of unit) -> one lane per unit st.async h to 8 CTAs + y STG.
//    NO __syncthreads in the loop.
// ---------------------------------------------------------------------------
__global__ void __cluster_dims__(8, 1, 1) __launch_bounds__(256, 1)
lstm_layer_kernel(const float* __restrict__ Whh, const float* __restrict__ gx,
                  float* __restrict__ y, const float* __restrict__ h0,
                  const float* __restrict__ c0, int layer)
{
    __shared__ __align__(16) float h_buf[2][256];
    __shared__ __align__(8) ull mbar[2];

    unsigned rank;
    asm("mov.u32 %0, %%cluster_ctarank;" : "=r"(rank));
    const int cluster_id = blockIdx.x >> 3;
    const int group = cluster_id & 3;
    const int dir   = cluster_id >> 2;
    const int tid  = threadIdx.x;
    const int lane = tid & 31;
    const int warp = tid >> 5;
    const int half = lane & 1;          // K-half of the dot
    const int gate = (lane >> 1) & 3;   // 0:i 1:f 2:g 3:o
    const int ug   = lane >> 3;         // unit within warp (0..3)
    const int unit_local = warp * 4 + ug;          // 0..31
    const int unit = (int)rank * 32 + unit_local;  // 0..255
    const int grow = gate * 256 + unit;            // global gate row

    // Whh slice (128 floats of row `grow`) into registers, f32x2 packed
    ulonglong2 w[32];
    const ulonglong2* wsrc = (const ulonglong2*)(Whh
        + ((long)(layer * 2 + dir) * 1024 + grow) * 256 + half * 128);
#pragma unroll
    for (int j = 0; j < 32; j++) w[j] = wsrc[j];

    // state init
    const int sidx = (layer * 2 + dir) * 256;
    h_buf[0][tid] = (group == 0) ? h0[sidx + tid] : 0.f;
    float creg = (group == 0) ? c0[sidx + unit] : 0.f;   // replicated in 8 lanes

    unsigned mb0 = smem_u32(&mbar[0]);
    unsigned mb1 = smem_u32(&mbar[1]);
    if (tid == 0) {
        mbar_init(mb0, 1);
        mbar_init(mb1, 1);
        mbar_arm(mb1, 1024);   // consumed at q=1
        mbar_arm(mb0, 1024);   // consumed at q=2
    }
    __syncthreads();
    cluster_sync_();

    const int xcol = dir * 1024 + grow;
    const int ycol = dir * 256 + unit;
    const long mbase = (long)group * 32 * 128;
    unsigned ph0 = 0, ph1 = 0;

    auto midx = [&](int q) -> long {
        int t = q & 127;
        if (dir) t = 127 - t;
        return mbase + (q & ~127) + t;
    };

    const bool is_x     = (half == 0);
    const bool is_store = (half == 0) && (gate == 0);
    const unsigned gbase = lane & 0x18;   // first lane of this unit's 8-lane group

    float xcur = is_x ? __ldg(gx + midx(0) * GXN + xcol) : 0.f;

    for (int q = 0; q < 4096; q++) {
        const int p = q & 1;

        float xnext = 0.f;
        if (is_x && q + 1 < 4096)
            xnext = __ldg(gx + midx(q + 1) * GXN + xcol);

        if (q > 0) {
            if (p) { mbar_wait(mb1, ph1); ph1 ^= 1; }
            else   { mbar_wait(mb0, ph0); ph0 ^= 1; }
            if (tid == 1) mbar_arm(p ? mb1 : mb0, 1024);   // re-arm for q+2
        }

        // half-dot: 128 MACs as 64 FFMA2, 4 accumulators
        const ulonglong2* hb = ((const ulonglong2*)h_buf[p]) + half * 32;
        ull a0 = 0, a1 = 0, a2 = 0, a3 = 0;
#pragma unroll
        for (int j = 0; j < 32; j += 2) {
            ulonglong2 hv = hb[j];
            fma2(a0, hv.x, w[j].x);
            fma2(a1, hv.y, w[j].y);
            ulonglong2 hv2 = hb[j + 1];
            fma2(a2, hv2.x, w[j + 1].x);
            fma2(a3, hv2.y, w[j + 1].y);
        }
        float s = (sum2(a0) + sum2(a1)) + (sum2(a2) + sum2(a3));
        s += __shfl_xor_sync(0xFFFFFFFFu, s, 1);   // combine K-halves
        s += xcur;                                  // valid on half==0 lanes
        // per-lane activation (only half==0 lanes' results are consumed)
        float act = (gate == 2) ? tanh_fast(s) : sigmoid_fast(s);
        // gather the 4 activated gates of this unit (from half==0 lanes)
        float ai = __shfl_sync(0xFFFFFFFFu, act, gbase + 0);
        float af = __shfl_sync(0xFFFFFFFFu, act, gbase + 2);
        float ag = __shfl_sync(0xFFFFFFFFu, act, gbase + 4);
        float ao = __shfl_sync(0xFFFFFFFFu, act, gbase + 6);
        creg = fmaf(af, creg, ai * ag);
        float h = ao * tanh_fast(creg);

        if (is_store) {
            const int pn = p ^ 1;
            unsigned ldst = smem_u32(&h_buf[pn][unit]);
            unsigned lbar = pn ? mb1 : mb0;
#pragma unroll
            for (unsigned r = 0; r < 8; r++)
                st_async_f32(mapa_cluster(ldst, r), h, mapa_cluster(lbar, r));
            y[midx(q) * Hn + ycol] = h;
        }
        xcur = xnext;
    }

    // absorb final unconsumed broadcast, leave together
    mbar_wait(mb0, ph0);
    cluster_sync_();
}

// ---------------------------------------------------------------------------
// 5) max over batch axis
// ---------------------------------------------------------------------------
__global__ void maxpool_kernel(const float* __restrict__ y1, float* __restrict__ out2)
{
    int idx = blockIdx.x * 256 + threadIdx.x;    // 0..65535
    int s = idx >> 9, h = idx & 511;
    float mx = -3.402823466e38f;
    for (int b = 0; b < 128; b++) {
        float v = y1[((long)b * 128 + s) * Hn + h];
        mx = fmaxf(mx, v);
    }
    out2[idx] = mx;
}

// ---------------------------------------------------------------------------
extern "C" void kernel_launch(void* const* d_in, const int* in_sizes, int n_in,
                              void* d_out, int out_size)
{
    const int*   rt  = (const int*)d_in[0];
    const int*   re  = (const int*)d_in[1];
    const int*   rm  = (const int*)d_in[2];
    const float* h0  = (const float*)d_in[3];
    const float* c0  = (const float*)d_in[4];
    const float* Ert = (const float*)d_in[5];
    const float* Ere = (const float*)d_in[6];
    const float* Erm = (const float*)d_in[7];
    const float* Wih = (const float*)d_in[8];   // (2,2,1024,512)
    const float* Whh = (const float*)d_in[9];   // (2,2,1024,256)
    const float* bih = (const float*)d_in[10];  // (2,2,1024)
    const float* bhh = (const float*)d_in[11];

    float* out  = (float*)d_out;
    float* y1   = out;                       // bilstm_outs (128,128,512)
    float* out2 = out + (long)Bn * Sn * Hn;  // output (128,512)

    void *p_emb = nullptr, *p_x = nullptr, *p_y0 = nullptr;
    cudaGetSymbolAddress(&p_emb, g_emb);
    cudaGetSymbolAddress(&p_x,   g_x);
    cudaGetSymbolAddress(&p_y0,  g_y0);
    float* emb = (float*)p_emb;
    float* gx  = (float*)p_x;
    float* y0  = (float*)p_y0;

    embed_kernel<<<NROW, 128>>>(rt, re, rm, Ert, Ere, Erm);

    dim3 ggrid(GXN / 64, NROW / 128);

    gemm_kernel<<<ggrid, 256>>>(emb, Wih, bih, bhh, gx);
    lstm_layer_kernel<<<64, 256>>>(Whh, gx, y0, h0, c0, 0);
    gemm_kernel<<<ggrid, 256>>>(y0, Wih + (long)1 * 2 * 1024 * 512,
                                bih + 2048, bhh + 2048, gx);
    lstm_layer_kernel<<<64, 256>>>(Whh, gx, y1, h0, c0, 1);
    maxpool_kernel<<<256, 256>>>(y1, out2);
}

// round 5
// speedup vs baseline: 1.2319x; 1.2319x over previous
#include <cuda_runtime.h>

// ---------------------------------------------------------------------------
// EncoderBiLSTMMaxPool: 2-layer bidirectional LSTM, hidden carried across
// samples, reset every 32 samples -> 4 independent chains x 2 dirs.
//
//   1. embed:  emb = E_rt[rt] + E_re[re] + E_rm[rm]          (16384 x 512)
//   2. gemm:   gx  = input @ Wih[l]^T + (bih+bhh)            (16384 x 2048)
//              FFMA2 inner loop, LDS.128-only smem reads
//   3. lstm:   recurrence (R3 structure), 8 clusters of 8 CTAs,
//              st.async + tx-counting mbarriers, precomputed DSMEM addrs
//   4. repeat 2,3 for layer 1 (into d_out)
//   5. maxpool over batch axis -> (S, H)
// ---------------------------------------------------------------------------

#define Bn   128
#define Sn   128
#define Hn   512
#define HHn  256
#define NROW 16384
#define GXN  2048

typedef unsigned long long ull;

__device__ float g_emb[NROW * Hn];
__device__ float g_x  [NROW * GXN];
__device__ float g_y0 [NROW * Hn];

// ---------------------------------------------------------------------------
// helpers
// ---------------------------------------------------------------------------
__device__ __forceinline__ unsigned smem_u32(const void* p) {
    return (unsigned)__cvta_generic_to_shared(p);
}
__device__ __forceinline__ unsigned mapa_cluster(unsigned addr, unsigned rank) {
    unsigned r;
    asm volatile("mapa.shared::cluster.u32 %0, %1, %2;" : "=r"(r) : "r"(addr), "r"(rank));
    return r;
}
__device__ __forceinline__ void cluster_sync_() {
    asm volatile("barrier.cluster.arrive.aligned;" ::: "memory");
    asm volatile("barrier.cluster.wait.aligned;" ::: "memory");
}
__device__ __forceinline__ void mbar_init(unsigned bar, unsigned cnt) {
    asm volatile("mbarrier.init.shared.b64 [%0], %1;" :: "r"(bar), "r"(cnt) : "memory");
}
__device__ __forceinline__ void mbar_arm(unsigned bar, unsigned tx) {
    asm volatile("mbarrier.arrive.expect_tx.shared::cta.b64 _, [%0], %1;"
                 :: "r"(bar), "r"(tx) : "memory");
}
__device__ __forceinline__ void mbar_wait(unsigned bar, unsigned parity) {
    asm volatile(
        "{\n\t.reg .pred P;\n"
        "LW%=:\n\t"
        "mbarrier.try_wait.parity.acquire.cta.shared::cta.b64 P, [%0], %1, 0x989680;\n\t"
        "@!P bra LW%=;\n\t}"
        :: "r"(bar), "r"(parity) : "memory");
}
__device__ __forceinline__ void st_async_f32(unsigned dst, float v, unsigned bar) {
    asm volatile("st.async.shared::cluster.mbarrier::complete_tx::bytes.b32 [%0], %1, [%2];"
                 :: "r"(dst), "r"(__float_as_uint(v)), "r"(bar) : "memory");
}
__device__ __forceinline__ float tanh_fast(float x) {
    float r;
    asm("tanh.approx.f32 %0, %1;" : "=f"(r) : "f"(x));
    return r;
}
__device__ __forceinline__ float sigmoid_fast(float x) {
    return fmaf(0.5f, tanh_fast(0.5f * x), 0.5f);
}
__device__ __forceinline__ void fma2(ull& acc, ull a, ull b) {
    asm("fma.rn.f32x2 %0, %1, %2, %0;" : "+l"(acc) : "l"(a), "l"(b));
}
__device__ __forceinline__ float sum2(ull a) {
    unsigned lo, hi;
    asm("mov.b64 {%0,%1}, %2;" : "=r"(lo), "=r"(hi) : "l"(a));
    return __uint_as_float(lo) + __uint_as_float(hi);
}
__device__ __forceinline__ void unpack2(ull a, float& lo, float& hi) {
    unsigned l, h;
    asm("mov.b64 {%0,%1}, %2;" : "=r"(l), "=r"(h) : "l"(a));
    lo = __uint_as_float(l); hi = __uint_as_float(h);
}

// ---------------------------------------------------------------------------
// 1) embedding sum
// ---------------------------------------------------------------------------
__global__ void embed_kernel(const int* __restrict__ rt, const int* __restrict__ re,
                             const int* __restrict__ rm,
                             const float* __restrict__ Ert, const float* __restrict__ Ere,
                             const float* __restrict__ Erm)
{
    int row = blockIdx.x;
    int t   = threadIdx.x;
    long irt = rt[row], ire = re[row], irm = rm[row];
    const float4* a = (const float4*)(Ert + irt * (long)Hn);
    const float4* b = (const float4*)(Ere + ire * (long)Hn);
    const float4* c = (const float4*)(Erm + irm * (long)Hn);
    float4 va = a[t], vb = b[t], vc = c[t];
    float4 o;
    o.x = va.x + vb.x + vc.x;
    o.y = va.y + vb.y + vc.y;
    o.z = va.z + vb.z + vc.z;
    o.w = va.w + vb.w + vc.w;
    ((float4*)(g_emb + (long)row * Hn))[t] = o;
}

// ---------------------------------------------------------------------------
// 2) fp32 GEMM, FFMA2 inner loop, LDS.128-only.
//    C[m,n] = sum_k A[m,k]*W[n,k] + bih[n] + bhh[n]
//    M=16384, N=2048, K=512. BM=128, BN=64, BK=16, 256 thr.
//    Thread (tx 0..15, ty 0..15): m = bm+ty*8+{0..7} (4 f32x2 m-pairs via
//    2x LDS.128), n = bn+tx*4+{0..3} (W duplicated (w,w) pairs, contiguous,
//    via 2x LDS.128). 16 FFMA2 per k. Epilogue: float4 STG.
// ---------------------------------------------------------------------------
__global__ __launch_bounds__(256) void gemm_kernel(
    const float* __restrict__ A, const float* __restrict__ W,
    const float* __restrict__ bih, const float* __restrict__ bhh,
    float* __restrict__ C)
{
    __shared__ __align__(16) float  As [16][128];
    __shared__ __align__(16) float2 Ws2[16][66];   // 64 used + pad (row=528B, 16B-aligned)

    const int bm = blockIdx.y * 128;
    const int bn = blockIdx.x * 64;
    const int tid = threadIdx.x;
    const int tx = tid & 15;
    const int ty = tid >> 4;

    ull acc[4][4];   // [m-pair i][n j]
#pragma unroll
    for (int i = 0; i < 4; i++)
#pragma unroll
        for (int j = 0; j < 4; j++) acc[i][j] = 0ull;

    for (int k0 = 0; k0 < 512; k0 += 16) {
        // A tile: 128x16, transposed into As[k][m]
#pragma unroll
        for (int i = 0; i < 2; i++) {
            int f4 = tid * 2 + i;
            int r = f4 >> 2, c4 = f4 & 3;
            float4 v = *(const float4*)(A + (long)(bm + r) * 512 + k0 + c4 * 4);
            As[c4 * 4 + 0][r] = v.x;
            As[c4 * 4 + 1][r] = v.y;
            As[c4 * 4 + 2][r] = v.z;
            As[c4 * 4 + 3][r] = v.w;
        }
        // W tile: 64x16, duplicated (w,w) pairs into Ws2[k][n]
        {
            int r = tid >> 2, c4 = tid & 3;
            float4 v = *(const float4*)(W + (long)(bn + r) * 512 + k0 + c4 * 4);
            Ws2[c4 * 4 + 0][r] = make_float2(v.x, v.x);
            Ws2[c4 * 4 + 1][r] = make_float2(v.y, v.y);
            Ws2[c4 * 4 + 2][r] = make_float2(v.z, v.z);
            Ws2[c4 * 4 + 3][r] = make_float2(v.w, v.w);
        }
        __syncthreads();
#pragma unroll
        for (int k = 0; k < 16; k++) {
            // 4 m-pairs: 2x LDS.128 (lane addr depends only on ty -> broadcast)
            ulonglong2 aq0 = *(const ulonglong2*)&As[k][ty * 8];
            ulonglong2 aq1 = *(const ulonglong2*)&As[k][ty * 8 + 4];
            // 4 n dup-pairs: 2x LDS.128 (contiguous at tx*4)
            const ulonglong2* wrow = (const ulonglong2*)&Ws2[k][0];
            ulonglong2 wq0 = wrow[tx * 2];
            ulonglong2 wq1 = wrow[tx * 2 + 1];
            ull a2[4] = { aq0.x, aq0.y, aq1.x, aq1.y };
            ull w2[4] = { wq0.x, wq0.y, wq1.x, wq1.y };
#pragma unroll
            for (int i = 0; i < 4; i++)
#pragma unroll
                for (int j = 0; j < 4; j++)
                    fma2(acc[i][j], a2[i], w2[j]);
        }
        __syncthreads();
    }

    const int n0 = bn + tx * 4;
    float4 b4a = *(const float4*)(bih + n0);
    float4 b4b = *(const float4*)(bhh + n0);
    float bias[4] = { b4a.x + b4b.x, b4a.y + b4b.y, b4a.z + b4b.z, b4a.w + b4b.w };

#pragma unroll
    for (int i = 0; i < 4; i++) {
        float lo[4], hi[4];
#pragma unroll
        for (int j = 0; j < 4; j++) unpack2(acc[i][j], lo[j], hi[j]);
        int m0 = bm + ty * 8 + 2 * i;
        float4 vlo = make_float4(lo[0] + bias[0], lo[1] + bias[1],
                                 lo[2] + bias[2], lo[3] + bias[3]);
        float4 vhi = make_float4(hi[0] + bias[0], hi[1] + bias[1],
                                 hi[2] + bias[2], hi[3] + bias[3]);
        *(float4*)(C + (long)m0 * GXN + n0)       = vlo;
        *(float4*)(C + (long)(m0 + 1) * GXN + n0) = vhi;
    }
}

// ---------------------------------------------------------------------------
// 3) LSTM recurrence (R3 structure). 8 clusters of 8 CTAs, 256 thr/CTA.
//    Thread: row_local = tid&127 (gate row in CTA), half = tid>>7 (K-half).
//    Per step: wait mbar[p] -> FFMA2 half-dot -> partial STS (+x) -> bar
//    -> 32 combiner lanes: gates, c,h -> y STG -> st.async h to 8 CTAs
//    (addresses fully precomputed per parity).
// ---------------------------------------------------------------------------
__global__ void __cluster_dims__(8, 1, 1) __launch_bounds__(256, 1)
lstm_layer_kernel(const float* __restrict__ Whh, const float* __restrict__ gx,
                  float* __restrict__ y, const float* __restrict__ h0,
                  const float* __restrict__ c0, int layer)
{
    __shared__ __align__(16) float h_buf[2][256];
    __shared__ float partial[256];
    __shared__ __align__(8) ull mbar[2];

    unsigned rank;
    asm("mov.u32 %0, %%cluster_ctarank;" : "=r"(rank));
    const int cluster_id = blockIdx.x >> 3;
    const int group = cluster_id & 3;
    const int dir   = cluster_id >> 2;
    const int tid = threadIdx.x;
    const int row_local = tid & 127;
    const int half = tid >> 7;
    const int gate = row_local >> 5;
    const int ul   = row_local & 31;
    const int unit = (int)rank * 32 + ul;
    const int grow = gate * 256 + unit;

    // Whh slice into registers, f32x2 packed
    ulonglong2 w[32];
    const ulonglong2* wsrc = (const ulonglong2*)(Whh
        + ((long)(layer * 2 + dir) * 1024 + grow) * 256 + half * 128);
#pragma unroll
    for (int j = 0; j < 32; j++) w[j] = wsrc[j];

    const int sidx = (layer * 2 + dir) * 256;
    h_buf[0][tid] = (group == 0) ? h0[sidx + tid] : 0.f;
    float creg = 0.f;
    if (tid < 32) creg = (group == 0) ? c0[sidx + (int)rank * 32 + tid] : 0.f;

    unsigned mb0 = smem_u32(&mbar[0]);
    unsigned mb1 = smem_u32(&mbar[1]);
    if (tid == 0) {
        mbar_init(mb0, 1);
        mbar_init(mb1, 1);
        mbar_arm(mb1, 1024);   // consumed at q=1
        mbar_arm(mb0, 1024);   // consumed at q=2
    }

    // precompute DSMEM targets (combiner lanes only use them; computed by all)
    unsigned dst0[8], bar0[8], dst1[8], bar1[8];
    {
        unsigned l0 = smem_u32(&h_buf[0][unit]);   // slot written when pn==0
        unsigned l1 = smem_u32(&h_buf[1][unit]);
#pragma unroll
        for (unsigned r = 0; r < 8; r++) {
            dst0[r] = mapa_cluster(l0, r);
            bar0[r] = mapa_cluster(mb0, r);
            dst1[r] = mapa_cluster(l1, r);
            bar1[r] = mapa_cluster(mb1, r);
        }
    }

    __syncthreads();
    cluster_sync_();

    const int xcol = dir * 1024 + grow;
    const int ycol = dir * 256 + unit;
    const long mbase = (long)group * 32 * 128;
    unsigned ph0 = 0, ph1 = 0;

    auto midx = [&](int q) -> long {
        int t = q & 127;
        if (dir) t = 127 - t;
        return mbase + (q & ~127) + t;
    };

    float xcur = (tid < 128) ? __ldg(gx + midx(0) * GXN + xcol) : 0.f;

    for (int q = 0; q < 4096; q++) {
        const int p = q & 1;

        float xnext = 0.f;
        if (tid < 128 && q + 1 < 4096)
            xnext = __ldg(gx + midx(q + 1) * GXN + xcol);

        if (q > 0) {
            if (p) { mbar_wait(mb1, ph1); ph1 ^= 1; }
            else   { mbar_wait(mb0, ph0); ph0 ^= 1; }
            if (tid == 32) mbar_arm(p ? mb1 : mb0, 1024);   // re-arm for q+2 (warp 1)
        }

        // half-dot: 128 MACs as 64 FFMA2
        const ulonglong2* hb = ((const ulonglong2*)h_buf[p]) + half * 32;
        ull a0 = 0, a1 = 0, a2 = 0, a3 = 0;
#pragma unroll
        for (int j = 0; j < 32; j += 2) {
            ulonglong2 hv = hb[j];
            fma2(a0, hv.x, w[j].x);
            fma2(a1, hv.y, w[j].y);
            ulonglong2 hv2 = hb[j + 1];
            fma2(a2, hv2.x, w[j + 1].x);
            fma2(a3, hv2.y, w[j + 1].y);
        }
        float s = (sum2(a0) + sum2(a1)) + (sum2(a2) + sum2(a3));
        partial[tid] = (tid < 128) ? (s + xcur) : s;
        __syncthreads();

        if (tid < 32) {
            float iv = partial[tid]      + partial[tid + 128];
            float fv = partial[tid + 32] + partial[tid + 160];
            float gv = partial[tid + 64] + partial[tid + 192];
            float ov = partial[tid + 96] + partial[tid + 224];
            float ig = sigmoid_fast(iv);
            float fg = sigmoid_fast(fv);
            float og = sigmoid_fast(ov);
            float gg = tanh_fast(gv);
            creg = fmaf(fg, creg, ig * gg);
            float h = og * tanh_fast(creg);

            if (p) {   // pn = 0
#pragma unroll
                for (unsigned r = 0; r < 8; r++) st_async_f32(dst0[r], h, bar0[r]);
            } else {   // pn = 1
#pragma unroll
                for (unsigned r = 0; r < 8; r++) st_async_f32(dst1[r], h, bar1[r]);
            }
            y[midx(q) * Hn + ycol] = h;
        }
        xcur = xnext;
    }

    mbar_wait(mb0, ph0);
    cluster_sync_();
}

// ---------------------------------------------------------------------------
// 5) max over batch axis
// ---------------------------------------------------------------------------
__global__ void maxpool_kernel(const float* __restrict__ y1, float* __restrict__ out2)
{
    int idx = blockIdx.x * 256 + threadIdx.x;    // 0..65535
    int s = idx >> 9, h = idx & 511;
    float mx = -3.402823466e38f;
    for (int b = 0; b < 128; b++) {
        float v = y1[((long)b * 128 + s) * Hn + h];
        mx = fmaxf(mx, v);
    }
    out2[idx] = mx;
}

// ---------------------------------------------------------------------------
extern "C" void kernel_launch(void* const* d_in, const int* in_sizes, int n_in,
                              void* d_out, int out_size)
{
    const int*   rt  = (const int*)d_in[0];
    const int*   re  = (const int*)d_in[1];
    const int*   rm  = (const int*)d_in[2];
    const float* h0  = (const float*)d_in[3];
    const float* c0  = (const float*)d_in[4];
    const float* Ert = (const float*)d_in[5];
    const float* Ere = (const float*)d_in[6];
    const float* Erm = (const float*)d_in[7];
    const float* Wih = (const float*)d_in[8];   // (2,2,1024,512)
    const float* Whh = (const float*)d_in[9];   // (2,2,1024,256)
    const float* bih = (const float*)d_in[10];  // (2,2,1024)
    const float* bhh = (const float*)d_in[11];

    float* out  = (float*)d_out;
    float* y1   = out;                       // bilstm_outs (128,128,512)
    float* out2 = out + (long)Bn * Sn * Hn;  // output (128,512)

    void *p_emb = nullptr, *p_x = nullptr, *p_y0 = nullptr;
    cudaGetSymbolAddress(&p_emb, g_emb);
    cudaGetSymbolAddress(&p_x,   g_x);
    cudaGetSymbolAddress(&p_y0,  g_y0);
    float* emb = (float*)p_emb;
    float* gx  = (float*)p_x;
    float* y0  = (float*)p_y0;

    embed_kernel<<<NROW, 128>>>(rt, re, rm, Ert, Ere, Erm);

    dim3 ggrid(GXN / 64, NROW / 128);

    gemm_kernel<<<ggrid, 256>>>(emb, Wih, bih, bhh, gx);
    lstm_layer_kernel<<<64, 256>>>(Whh, gx, y0, h0, c0, 0);
    gemm_kernel<<<ggrid, 256>>>(y0, Wih + (long)1 * 2 * 1024 * 512,
                                bih + 2048, bhh + 2048, gx);
    lstm_layer_kernel<<<64, 256>>>(Whh, gx, y1, h0, c0, 1);
    maxpool_kernel<<<256, 256>>>(y1, out2);
}

// round 6
// speedup vs baseline: 1.4761x; 1.1983x over previous
#include <cuda_runtime.h>

// ---------------------------------------------------------------------------
// EncoderBiLSTMMaxPool: 2-layer bidirectional LSTM, hidden carried across
// samples, reset every 32 samples -> 4 independent chains x 2 dirs.
//
//   1. embed:  emb = E_rt[rt] + E_re[re] + E_rm[rm]          (16384 x 512)
//   2. gemm:   gx  = input @ Wih[l]^T + (bih+bhh)            (16384 x 2048)
//              plain-FFMA 8x8 microtile (BM=128,BN=128,BK=16)
//   3. lstm:   recurrence (R3 verbatim), 8 clusters of 8 CTAs,
//              st.async + tx-counting mbarriers
//   4. repeat 2,3 for layer 1 (into d_out)
//   5. maxpool over batch axis -> (S, H)
// ---------------------------------------------------------------------------

#define Bn   128
#define Sn   128
#define Hn   512
#define HHn  256
#define NROW 16384
#define GXN  2048

typedef unsigned long long ull;

__device__ float g_emb[NROW * Hn];
__device__ float g_x  [NROW * GXN];
__device__ float g_y0 [NROW * Hn];

// ---------------------------------------------------------------------------
// helpers
// ---------------------------------------------------------------------------
__device__ __forceinline__ unsigned smem_u32(const void* p) {
    return (unsigned)__cvta_generic_to_shared(p);
}
__device__ __forceinline__ unsigned mapa_cluster(unsigned addr, unsigned rank) {
    unsigned r;
    asm volatile("mapa.shared::cluster.u32 %0, %1, %2;" : "=r"(r) : "r"(addr), "r"(rank));
    return r;
}
__device__ __forceinline__ void cluster_sync_() {
    asm volatile("barrier.cluster.arrive.aligned;" ::: "memory");
    asm volatile("barrier.cluster.wait.aligned;" ::: "memory");
}
__device__ __forceinline__ void mbar_init(unsigned bar, unsigned cnt) {
    asm volatile("mbarrier.init.shared.b64 [%0], %1;" :: "r"(bar), "r"(cnt) : "memory");
}
__device__ __forceinline__ void mbar_arm(unsigned bar, unsigned tx) {
    asm volatile("mbarrier.arrive.expect_tx.shared::cta.b64 _, [%0], %1;"
                 :: "r"(bar), "r"(tx) : "memory");
}
__device__ __forceinline__ void mbar_wait(unsigned bar, unsigned parity) {
    asm volatile(
        "{\n\t.reg .pred P;\n"
        "LW%=:\n\t"
        "mbarrier.try_wait.parity.acquire.cta.shared::cta.b64 P, [%0], %1, 0x989680;\n\t"
        "@!P bra LW%=;\n\t}"
        :: "r"(bar), "r"(parity) : "memory");
}
__device__ __forceinline__ void st_async_f32(unsigned dst, float v, unsigned bar) {
    asm volatile("st.async.shared::cluster.mbarrier::complete_tx::bytes.b32 [%0], %1, [%2];"
                 :: "r"(dst), "r"(__float_as_uint(v)), "r"(bar) : "memory");
}
__device__ __forceinline__ float tanh_fast(float x) {
    float r;
    asm("tanh.approx.f32 %0, %1;" : "=f"(r) : "f"(x));
    return r;
}
__device__ __forceinline__ float sigmoid_fast(float x) {
    return fmaf(0.5f, tanh_fast(0.5f * x), 0.5f);
}
__device__ __forceinline__ void fma2(ull& acc, ull a, ull b) {
    asm("fma.rn.f32x2 %0, %1, %2, %0;" : "+l"(acc) : "l"(a), "l"(b));
}
__device__ __forceinline__ float sum2(ull a) {
    unsigned lo, hi;
    asm("mov.b64 {%0,%1}, %2;" : "=r"(lo), "=r"(hi) : "l"(a));
    return __uint_as_float(lo) + __uint_as_float(hi);
}

// ---------------------------------------------------------------------------
// 1) embedding sum
// ---------------------------------------------------------------------------
__global__ void embed_kernel(const int* __restrict__ rt, const int* __restrict__ re,
                             const int* __restrict__ rm,
                             const float* __restrict__ Ert, const float* __restrict__ Ere,
                             const float* __restrict__ Erm)
{
    int row = blockIdx.x;
    int t   = threadIdx.x;
    long irt = rt[row], ire = re[row], irm = rm[row];
    const float4* a = (const float4*)(Ert + irt * (long)Hn);
    const float4* b = (const float4*)(Ere + ire * (long)Hn);
    const float4* c = (const float4*)(Erm + irm * (long)Hn);
    float4 va = a[t], vb = b[t], vc = c[t];
    float4 o;
    o.x = va.x + vb.x + vc.x;
    o.y = va.y + vb.y + vc.y;
    o.z = va.z + vb.z + vc.z;
    o.w = va.w + vb.w + vc.w;
    ((float4*)(g_emb + (long)row * Hn))[t] = o;
}

// ---------------------------------------------------------------------------
// 2) fp32 GEMM, plain FFMA, 8x8 microtile.
//    C[m,n] = sum_k A[m,k]*W[n,k] + bih[n] + bhh[n]
//    M=16384, N=2048, K=512. BM=128, BN=128, BK=16, 256 thr (tx 0..15, ty 0..15).
//    Thread tile: m = bm + ty*4 + {0..3} and + 64, n = bn + tx*4 + {0..3} and + 64.
//    Per k: 4x LDS.128 (all conflict-free contiguous groups) + 64 FFMA.
// ---------------------------------------------------------------------------
__global__ __launch_bounds__(256) void gemm_kernel(
    const float* __restrict__ A, const float* __restrict__ W,
    const float* __restrict__ bih, const float* __restrict__ bhh,
    float* __restrict__ C)
{
    __shared__ __align__(16) float As[16][128];
    __shared__ __align__(16) float Ws[16][128];

    const int bm = blockIdx.y * 128;
    const int bn = blockIdx.x * 128;
    const int tid = threadIdx.x;
    const int tx = tid & 15;
    const int ty = tid >> 4;

    float acc[8][8];
#pragma unroll
    for (int i = 0; i < 8; i++)
#pragma unroll
        for (int j = 0; j < 8; j++) acc[i][j] = 0.f;

    for (int k0 = 0; k0 < 512; k0 += 16) {
        // A tile: 128x16 -> As[k][m]; 512 float4 loads, 2 per thread
#pragma unroll
        for (int i = 0; i < 2; i++) {
            int f4 = tid * 2 + i;
            int r = f4 >> 2, c4 = f4 & 3;
            float4 v = *(const float4*)(A + (long)(bm + r) * 512 + k0 + c4 * 4);
            As[c4 * 4 + 0][r] = v.x;
            As[c4 * 4 + 1][r] = v.y;
            As[c4 * 4 + 2][r] = v.z;
            As[c4 * 4 + 3][r] = v.w;
        }
        // W tile: 128x16 -> Ws[k][n]; same pattern
#pragma unroll
        for (int i = 0; i < 2; i++) {
            int f4 = tid * 2 + i;
            int r = f4 >> 2, c4 = f4 & 3;
            float4 v = *(const float4*)(W + (long)(bn + r) * 512 + k0 + c4 * 4);
            Ws[c4 * 4 + 0][r] = v.x;
            Ws[c4 * 4 + 1][r] = v.y;
            Ws[c4 * 4 + 2][r] = v.z;
            Ws[c4 * 4 + 3][r] = v.w;
        }
        __syncthreads();
#pragma unroll
        for (int k = 0; k < 16; k++) {
            float a[8], w[8];
            *(float4*)(a)     = *(const float4*)&As[k][ty * 4];
            *(float4*)(a + 4) = *(const float4*)&As[k][64 + ty * 4];
            *(float4*)(w)     = *(const float4*)&Ws[k][tx * 4];
            *(float4*)(w + 4) = *(const float4*)&Ws[k][64 + tx * 4];
#pragma unroll
            for (int i = 0; i < 8; i++)
#pragma unroll
                for (int j = 0; j < 8; j++)
                    acc[i][j] += a[i] * w[j];
        }
        __syncthreads();
    }

    // epilogue: 2x2 blocks of 4x4, float4 stores
#pragma unroll
    for (int jj = 0; jj < 2; jj++) {
        int n0 = bn + tx * 4 + jj * 64;
        float4 ba = *(const float4*)(bih + n0);
        float4 bb = *(const float4*)(bhh + n0);
        float4 bias = make_float4(ba.x + bb.x, ba.y + bb.y, ba.z + bb.z, ba.w + bb.w);
#pragma unroll
        for (int ii = 0; ii < 2; ii++) {
#pragma unroll
            for (int i2 = 0; i2 < 4; i2++) {
                int m = bm + ty * 4 + ii * 64 + i2;
                int ai = ii * 4 + i2;
                float4 v;
                v.x = acc[ai][jj * 4 + 0] + bias.x;
                v.y = acc[ai][jj * 4 + 1] + bias.y;
                v.z = acc[ai][jj * 4 + 2] + bias.z;
                v.w = acc[ai][jj * 4 + 3] + bias.w;
                *(float4*)(C + (long)m * GXN + n0) = v;
            }
        }
    }
}

// ---------------------------------------------------------------------------
// 3) LSTM recurrence (R3 verbatim — measured 4.2ms). 8 clusters of 8 CTAs.
// ---------------------------------------------------------------------------
__global__ void __cluster_dims__(8, 1, 1) __launch_bounds__(256, 1)
lstm_layer_kernel(const float* __restrict__ Whh, const float* __restrict__ gx,
                  float* __restrict__ y, const float* __restrict__ h0,
                  const float* __restrict__ c0, int layer)
{
    __shared__ __align__(16) float h_buf[2][256];
    __shared__ float partial[256];
    __shared__ __align__(8) ull mbar[2];

    unsigned rank;
    asm("mov.u32 %0, %%cluster_ctarank;" : "=r"(rank));
    const int cluster_id = blockIdx.x >> 3;
    const int group = cluster_id & 3;
    const int dir   = cluster_id >> 2;
    const int tid = threadIdx.x;
    const int row_local = tid & 127;
    const int half = tid >> 7;
    const int gate = row_local >> 5;
    const int ul   = row_local & 31;
    const int unit = (int)rank * 32 + ul;
    const int grow = gate * 256 + unit;

    ulonglong2 w[32];
    const ulonglong2* wsrc = (const ulonglong2*)(Whh
        + ((long)(layer * 2 + dir) * 1024 + grow) * 256 + half * 128);
#pragma unroll
    for (int j = 0; j < 32; j++) w[j] = wsrc[j];

    const int sidx = (layer * 2 + dir) * 256;
    h_buf[0][tid] = (group == 0) ? h0[sidx + tid] : 0.f;
    float creg = 0.f;
    if (tid < 32) creg = (group == 0) ? c0[sidx + (int)rank * 32 + tid] : 0.f;

    unsigned mb0 = smem_u32(&mbar[0]);
    unsigned mb1 = smem_u32(&mbar[1]);
    if (tid == 0) {
        mbar_init(mb0, 1);
        mbar_init(mb1, 1);
        mbar_arm(mb1, 1024);   // consumed at q=1
        mbar_arm(mb0, 1024);   // consumed at q=2
    }
    __syncthreads();
    cluster_sync_();

    const int xcol = dir * 1024 + grow;
    const int ycol = dir * 256 + unit;
    const long mbase = (long)group * 32 * 128;
    unsigned ph0 = 0, ph1 = 0;

    auto midx = [&](int q) -> long {
        int t = q & 127;
        if (dir) t = 127 - t;
        return mbase + (q & ~127) + t;
    };

    float xcur = (tid < 128) ? __ldg(gx + midx(0) * GXN + xcol) : 0.f;

    for (int q = 0; q < 4096; q++) {
        const int p = q & 1;

        float xnext = 0.f;
        if (tid < 128 && q + 1 < 4096)
            xnext = __ldg(gx + midx(q + 1) * GXN + xcol);

        if (q > 0) {
            if (p) { mbar_wait(mb1, ph1); ph1 ^= 1; }
            else   { mbar_wait(mb0, ph0); ph0 ^= 1; }
            if (tid == 1) mbar_arm(p ? mb1 : mb0, 1024);   // re-arm for q+2
        }

        // half-dot: 128 MACs as 64 FFMA2
        const ulonglong2* hb = ((const ulonglong2*)h_buf[p]) + half * 32;
        ull acc0 = 0, acc1 = 0;
#pragma unroll
        for (int j = 0; j < 32; j++) {
            ulonglong2 hv = hb[j];
            fma2(acc0, hv.x, w[j].x);
            fma2(acc1, hv.y, w[j].y);
        }
        float s = sum2(acc0) + sum2(acc1);
        partial[tid] = (tid < 128) ? (s + xcur) : s;
        __syncthreads();

        if (tid < 32) {
            float iv = partial[tid]      + partial[tid + 128];
            float fv = partial[tid + 32] + partial[tid + 160];
            float gv = partial[tid + 64] + partial[tid + 192];
            float ov = partial[tid + 96] + partial[tid + 224];
            float ig = sigmoid_fast(iv);
            float fg = sigmoid_fast(fv);
            float og = sigmoid_fast(ov);
            float gg = tanh_fast(gv);
            creg = fmaf(fg, creg, ig * gg);
            float h = og * tanh_fast(creg);
            y[midx(q) * Hn + ycol] = h;

            const int pn = p ^ 1;
            unsigned ldst = smem_u32(&h_buf[pn][unit]);
            unsigned lbar = pn ? mb1 : mb0;
#pragma unroll
            for (unsigned r = 0; r < 8; r++)
                st_async_f32(mapa_cluster(ldst, r), h, mapa_cluster(lbar, r));
        }
        xcur = xnext;
    }

    mbar_wait(mb0, ph0);
    cluster_sync_();
}

// ---------------------------------------------------------------------------
// 5) max over batch axis
// ---------------------------------------------------------------------------
__global__ void maxpool_kernel(const float* __restrict__ y1, float* __restrict__ out2)
{
    int idx = blockIdx.x * 256 + threadIdx.x;    // 0..65535
    int s = idx >> 9, h = idx & 511;
    float mx = -3.402823466e38f;
    for (int b = 0; b < 128; b++) {
        float v = y1[((long)b * 128 + s) * Hn + h];
        mx = fmaxf(mx, v);
    }
    out2[idx] = mx;
}

// ---------------------------------------------------------------------------
extern "C" void kernel_launch(void* const* d_in, const int* in_sizes, int n_in,
                              void* d_out, int out_size)
{
    const int*   rt  = (const int*)d_in[0];
    const int*   re  = (const int*)d_in[1];
    const int*   rm  = (const int*)d_in[2];
    const float* h0  = (const float*)d_in[3];
    const float* c0  = (const float*)d_in[4];
    const float* Ert = (const float*)d_in[5];
    const float* Ere = (const float*)d_in[6];
    const float* Erm = (const float*)d_in[7];
    const float* Wih = (const float*)d_in[8];   // (2,2,1024,512)
    const float* Whh = (const float*)d_in[9];   // (2,2,1024,256)
    const float* bih = (const float*)d_in[10];  // (2,2,1024)
    const float* bhh = (const float*)d_in[11];

    float* out  = (float*)d_out;
    float* y1   = out;                       // bilstm_outs (128,128,512)
    float* out2 = out + (long)Bn * Sn * Hn;  // output (128,512)

    void *p_emb = nullptr, *p_x = nullptr, *p_y0 = nullptr;
    cudaGetSymbolAddress(&p_emb, g_emb);
    cudaGetSymbolAddress(&p_x,   g_x);
    cudaGetSymbolAddress(&p_y0,  g_y0);
    float* emb = (float*)p_emb;
    float* gx  = (float*)p_x;
    float* y0  = (float*)p_y0;

    embed_kernel<<<NROW, 128>>>(rt, re, rm, Ert, Ere, Erm);

    dim3 ggrid(GXN / 128, NROW / 128);   // (16, 128)

    gemm_kernel<<<ggrid, 256>>>(emb, Wih, bih, bhh, gx);
    lstm_layer_kernel<<<64, 256>>>(Whh, gx, y0, h0, c0, 0);
    gemm_kernel<<<ggrid, 256>>>(y0, Wih + (long)1 * 2 * 1024 * 512,
                                bih + 2048, bhh + 2048, gx);
    lstm_layer_kernel<<<64, 256>>>(Whh, gx, y1, h0, c0, 1);
    maxpool_kernel<<<256, 256>>>(y1, out2);
}

// round 8
// speedup vs baseline: 1.7046x; 1.1548x over previous
#include <cuda_runtime.h>
#include <cuda_bf16.h>
#include <cstdint>

// ---------------------------------------------------------------------------
// EncoderBiLSTMMaxPool on GB300 (compute_103 baseline PTX only — no tcgen05):
//   1. embed_split: a2 = split_bf16(E_rt[rt]+E_re[re]+E_rm[rm])  [16384 x 1536]
//   2. w_split:     w2 = split_bf16(Wih)                         [2][2048 x 1536]
//   3. gemm_mma:    gx = a2 @ w2[l]^T + bias   (mma.sync bf16, K=1536 3-term
//                   hi/lo split => fp32-accurate to ~1e-5)
//   4. lstm:        recurrence (R6 verbatim), 8 clusters of 8 CTAs
//   5. y_split -> gemm -> lstm (layer 1) -> maxpool
// ---------------------------------------------------------------------------

#define Bn   128
#define Sn   128
#define Hn   512
#define NROW 16384
#define GXN  2048
#define KSPL 1536            // split-K: [hi | lo | hi] vs [hi | hi | lo]

typedef unsigned long long ull;

__device__ __align__(16) float          g_x [NROW * GXN];
__device__ __align__(16) float          g_y0[NROW * Hn];
__device__ __align__(16) __nv_bfloat16  g_a2[(long)NROW * KSPL];
__device__ __align__(16) __nv_bfloat16  g_w2[2L * GXN * KSPL];

// ---------------------------------------------------------------------------
// common helpers
// ---------------------------------------------------------------------------
__device__ __forceinline__ unsigned smem_u32(const void* p) {
    return (unsigned)__cvta_generic_to_shared(p);
}
__device__ __forceinline__ unsigned mapa_cluster(unsigned addr, unsigned rank) {
    unsigned r;
    asm volatile("mapa.shared::cluster.u32 %0, %1, %2;" : "=r"(r) : "r"(addr), "r"(rank));
    return r;
}
__device__ __forceinline__ void cluster_sync_() {
    asm volatile("barrier.cluster.arrive.aligned;" ::: "memory");
    asm volatile("barrier.cluster.wait.aligned;" ::: "memory");
}
__device__ __forceinline__ void mbar_init(unsigned bar, unsigned cnt) {
    asm volatile("mbarrier.init.shared.b64 [%0], %1;" :: "r"(bar), "r"(cnt) : "memory");
}
__device__ __forceinline__ void mbar_arm(unsigned bar, unsigned tx) {
    asm volatile("mbarrier.arrive.expect_tx.shared::cta.b64 _, [%0], %1;"
                 :: "r"(bar), "r"(tx) : "memory");
}
__device__ __forceinline__ void mbar_wait(unsigned bar, unsigned parity) {
    asm volatile(
        "{\n\t.reg .pred P;\n"
        "LW%=:\n\t"
        "mbarrier.try_wait.parity.acquire.cta.shared::cta.b64 P, [%0], %1, 0x989680;\n\t"
        "@!P bra LW%=;\n\t}"
        :: "r"(bar), "r"(parity) : "memory");
}
__device__ __forceinline__ void st_async_f32(unsigned dst, float v, unsigned bar) {
    asm volatile("st.async.shared::cluster.mbarrier::complete_tx::bytes.b32 [%0], %1, [%2];"
                 :: "r"(dst), "r"(__float_as_uint(v)), "r"(bar) : "memory");
}
__device__ __forceinline__ float tanh_fast(float x) {
    float r;
    asm("tanh.approx.f32 %0, %1;" : "=f"(r) : "f"(x));
    return r;
}
__device__ __forceinline__ float sigmoid_fast(float x) {
    return fmaf(0.5f, tanh_fast(0.5f * x), 0.5f);
}
__device__ __forceinline__ void fma2(ull& acc, ull a, ull b) {
    asm("fma.rn.f32x2 %0, %1, %2, %0;" : "+l"(acc) : "l"(a), "l"(b));
}
__device__ __forceinline__ float sum2(ull a) {
    unsigned lo, hi;
    asm("mov.b64 {%0,%1}, %2;" : "=r"(lo), "=r"(hi) : "l"(a));
    return __uint_as_float(lo) + __uint_as_float(hi);
}

// --- mma.sync / ldmatrix / cp.async helpers (all baseline PTX ISA) ---
__device__ __forceinline__ void cp16(unsigned dst, const void* src) {
    asm volatile("cp.async.cg.shared.global [%0], [%1], 16;" :: "r"(dst), "l"(src));
}
__device__ __forceinline__ void cp_commit() {
    asm volatile("cp.async.commit_group;" ::: "memory");
}
__device__ __forceinline__ void cp_wait2() {
    asm volatile("cp.async.wait_group 2;" ::: "memory");
}
__device__ __forceinline__ void ldsm4(unsigned* r, unsigned addr) {
    asm volatile("ldmatrix.sync.aligned.m8n8.x4.shared.b16 {%0,%1,%2,%3}, [%4];"
                 : "=r"(r[0]), "=r"(r[1]), "=r"(r[2]), "=r"(r[3]) : "r"(addr));
}
__device__ __forceinline__ void mma16816(float* c, const unsigned* a,
                                         unsigned b0, unsigned b1) {
    asm volatile(
        "mma.sync.aligned.m16n8k16.row.col.f32.bf16.bf16.f32 "
        "{%0,%1,%2,%3}, {%4,%5,%6,%7}, {%8,%9}, {%0,%1,%2,%3};"
        : "+f"(c[0]), "+f"(c[1]), "+f"(c[2]), "+f"(c[3])
        : "r"(a[0]), "r"(a[1]), "r"(a[2]), "r"(a[3]), "r"(b0), "r"(b1));
}

// hi/lo bf16 split pack
__device__ __forceinline__ uint2 pack4bf16(float a, float b, float c, float d) {
    __nv_bfloat162 p0 = __floats2bfloat162_rn(a, b);
    __nv_bfloat162 p1 = __floats2bfloat162_rn(c, d);
    uint2 r;
    r.x = *(unsigned*)&p0;
    r.y = *(unsigned*)&p1;
    return r;
}
__device__ __forceinline__ void split4(const float* v, float* hi, float* lo) {
#pragma unroll
    for (int j = 0; j < 4; j++) {
        __nv_bfloat16 h = __float2bfloat16_rn(v[j]);
        hi[j] = __bfloat162float(h);
        lo[j] = v[j] - hi[j];
    }
}

// ---------------------------------------------------------------------------
// 1) embedding sum + split -> a2 rows [hi | lo | hi]
// ---------------------------------------------------------------------------
__global__ void embed_split_kernel(const int* __restrict__ rt, const int* __restrict__ re,
                                   const int* __restrict__ rm,
                                   const float* __restrict__ Ert, const float* __restrict__ Ere,
                                   const float* __restrict__ Erm)
{
    int row = blockIdx.x;
    int t   = threadIdx.x;     // 0..127, 4 cols each
    long irt = rt[row], ire = re[row], irm = rm[row];
    float4 va = ((const float4*)(Ert + irt * (long)Hn))[t];
    float4 vb = ((const float4*)(Ere + ire * (long)Hn))[t];
    float4 vc = ((const float4*)(Erm + irm * (long)Hn))[t];
    float v[4] = { va.x + vb.x + vc.x, va.y + vb.y + vc.y,
                   va.z + vb.z + vc.z, va.w + vb.w + vc.w };
    float hi[4], lo[4];
    split4(v, hi, lo);
    __nv_bfloat16* ro = g_a2 + (long)row * KSPL + 4 * t;
    uint2 ph = pack4bf16(hi[0], hi[1], hi[2], hi[3]);
    *(uint2*)(ro)        = ph;                                    // block0: hi
    *(uint2*)(ro + 512)  = pack4bf16(lo[0], lo[1], lo[2], lo[3]); // block1: lo
    *(uint2*)(ro + 1024) = ph;                                    // block2: hi
}

__global__ void y_split_kernel(const float* __restrict__ y0)
{
    int row = blockIdx.x;
    int t   = threadIdx.x;
    float4 vv = ((const float4*)(y0 + (long)row * Hn))[t];
    float v[4] = { vv.x, vv.y, vv.z, vv.w };
    float hi[4], lo[4];
    split4(v, hi, lo);
    __nv_bfloat16* ro = g_a2 + (long)row * KSPL + 4 * t;
    uint2 ph = pack4bf16(hi[0], hi[1], hi[2], hi[3]);
    *(uint2*)(ro)        = ph;
    *(uint2*)(ro + 512)  = pack4bf16(lo[0], lo[1], lo[2], lo[3]);
    *(uint2*)(ro + 1024) = ph;
}

// split Wih -> w2 rows [hi | hi | lo]
__global__ void w_split_kernel(const float* __restrict__ Wih)
{
    int n = blockIdx.x;        // 0..2047
    int l = blockIdx.y;        // layer
    int t = threadIdx.x;
    float4 vv = *(const float4*)(Wih + ((long)l * 2048 + n) * 512 + 4 * t);
    float v[4] = { vv.x, vv.y, vv.z, vv.w };
    float hi[4], lo[4];
    split4(v, hi, lo);
    __nv_bfloat16* ro = g_w2 + ((long)l * 2048 + n) * KSPL + 4 * t;
    uint2 ph = pack4bf16(hi[0], hi[1], hi[2], hi[3]);
    *(uint2*)(ro)        = ph;                                    // block0: hi
    *(uint2*)(ro + 512)  = ph;                                    // block1: hi
    *(uint2*)(ro + 1024) = pack4bf16(lo[0], lo[1], lo[2], lo[3]); // block2: lo
}

// ---------------------------------------------------------------------------
// 2) mma.sync bf16 GEMM:  C[m,n] = sum_k a2[m,k]*w2[n,k] + bih[n]+bhh[n]
//    Block 128x128, warps 4(m)x2(n), warp tile 32x64. K=1536, BK=32.
//    smem rows at 80B stride -> conflict-free ldmatrix, no swizzle.
//    3-stage cp.async pipeline.
// ---------------------------------------------------------------------------
#define ROWB       80                       // smem row stride (bytes)
#define A_BYTES    (128 * ROWB)             // 10240
#define STAGE_B    (2 * A_BYTES)            // A + B per stage = 20480
#define GEMM_SMEM  (3 * STAGE_B)            // 61440
#define NKT        (KSPL / 32)              // 48 k-tiles

__global__ __launch_bounds__(256, 2) void gemm_mma_kernel(
    const __nv_bfloat16* __restrict__ A2, const __nv_bfloat16* __restrict__ W2,
    const float* __restrict__ bih, const float* __restrict__ bhh,
    float* __restrict__ C)
{
    extern __shared__ __align__(16) char dyn[];
    __shared__ float bias_s[128];

    const int tid  = threadIdx.x;
    const int wid  = tid >> 5;
    const int lane = tid & 31;
    const int wm   = wid & 3;        // warp m-tile (32 rows)
    const int wn   = wid >> 2;       // warp n-tile (64 cols)
    const int bm = blockIdx.y * 128;
    const int bn = blockIdx.x * 128;

    if (tid < 128) bias_s[tid] = bih[bn + tid] + bhh[bn + tid];

    const unsigned sbase = smem_u32(dyn);

    // per-lane ldmatrix address pieces
    const int g  = lane >> 3;        // matrix id within x4
    const int rr = lane & 7;
    // A: row = wm*32 + mi*16 + (g&1)*8 + rr ; chunk = kk*2 + (g>>1)
    const unsigned a_lane = (unsigned)((wm * 32 + (g & 1) * 8 + rr) * ROWB + (g >> 1) * 16);
    // B: row = wn*64 + nj2*16 + (g>>1)*8 + rr ; chunk = kk*2 + (g&1)
    const unsigned b_lane = (unsigned)((wn * 64 + (g >> 1) * 8 + rr) * ROWB + (g & 1) * 16);

    float acc[2][8][4];
#pragma unroll
    for (int i = 0; i < 2; i++)
#pragma unroll
        for (int j = 0; j < 8; j++)
#pragma unroll
            for (int q = 0; q < 4; q++) acc[i][j][q] = 0.f;

    // loads: 1024 x 16B chunks per stage (A: 512, B: 512), 4 per thread
    auto issue_loads = [&](int kt) {
        unsigned stage = sbase + (unsigned)(kt % 3) * STAGE_B;
        long k0 = (long)kt * 32;
#pragma unroll
        for (int i = 0; i < 4; i++) {
            int c = tid + i * 256;
            if (c < 512) {
                int row = c >> 2, ch = c & 3;
                cp16(stage + row * ROWB + ch * 16,
                     A2 + (long)(bm + row) * KSPL + k0 + ch * 8);
            } else {
                int c2 = c - 512;
                int row = c2 >> 2, ch = c2 & 3;
                cp16(stage + A_BYTES + row * ROWB + ch * 16,
                     W2 + (long)(bn + row) * KSPL + k0 + ch * 8);
            }
        }
    };

    issue_loads(0); cp_commit();
    issue_loads(1); cp_commit();
    issue_loads(2); cp_commit();

    for (int kt = 0; kt < NKT; kt++) {
        cp_wait2();
        __syncthreads();
        unsigned stage  = sbase + (unsigned)(kt % 3) * STAGE_B;
        unsigned stageB = stage + A_BYTES;
#pragma unroll
        for (int kk = 0; kk < 2; kk++) {
            unsigned afrag[2][4];
#pragma unroll
            for (int mi = 0; mi < 2; mi++)
                ldsm4(afrag[mi], stage + a_lane + mi * 16 * ROWB + kk * 32);
            unsigned bfrag[4][4];
#pragma unroll
            for (int p = 0; p < 4; p++)
                ldsm4(bfrag[p], stageB + b_lane + p * 16 * ROWB + kk * 32);
#pragma unroll
            for (int mi = 0; mi < 2; mi++)
#pragma unroll
                for (int p = 0; p < 4; p++) {
                    mma16816(acc[mi][2 * p],     afrag[mi], bfrag[p][0], bfrag[p][1]);
                    mma16816(acc[mi][2 * p + 1], afrag[mi], bfrag[p][2], bfrag[p][3]);
                }
        }
        __syncthreads();
        if (kt + 3 < NKT) issue_loads(kt + 3);
        cp_commit();
    }

    // epilogue: thread t holds (row = base + t/4 [+8], col = nj*8 + (t%4)*2)
    const int trow = lane >> 2;
    const int tcol = (lane & 3) * 2;
#pragma unroll
    for (int mi = 0; mi < 2; mi++) {
        int m0 = bm + wm * 32 + mi * 16 + trow;
#pragma unroll
        for (int nj = 0; nj < 8; nj++) {
            int cl = wn * 64 + nj * 8 + tcol;       // block-local col
            int n0 = bn + cl;
            float b0 = bias_s[cl], b1 = bias_s[cl + 1];
            *(float2*)(C + (long)m0 * GXN + n0) =
                make_float2(acc[mi][nj][0] + b0, acc[mi][nj][1] + b1);
            *(float2*)(C + (long)(m0 + 8) * GXN + n0) =
                make_float2(acc[mi][nj][2] + b0, acc[mi][nj][3] + b1);
        }
    }
}

// ---------------------------------------------------------------------------
// 3) LSTM recurrence (R6 verbatim — measured ~2.09ms/layer).
// ---------------------------------------------------------------------------
__global__ void __cluster_dims__(8, 1, 1) __launch_bounds__(256, 1)
lstm_layer_kernel(const float* __restrict__ Whh, const float* __restrict__ gx,
                  float* __restrict__ y, const float* __restrict__ h0,
                  const float* __restrict__ c0, int layer)
{
    __shared__ __align__(16) float h_buf[2][256];
    __shared__ float partial[256];
    __shared__ __align__(8) ull mbar[2];

    unsigned rank;
    asm("mov.u32 %0, %%cluster_ctarank;" : "=r"(rank));
    const int cluster_id = blockIdx.x >> 3;
    const int group = cluster_id & 3;
    const int dir   = cluster_id >> 2;
    const int tid = threadIdx.x;
    const int row_local = tid & 127;
    const int half = tid >> 7;
    const int gate = row_local >> 5;
    const int ul   = row_local & 31;
    const int unit = (int)rank * 32 + ul;
    const int grow = gate * 256 + unit;

    ulonglong2 w[32];
    const ulonglong2* wsrc = (const ulonglong2*)(Whh
        + ((long)(layer * 2 + dir) * 1024 + grow) * 256 + half * 128);
#pragma unroll
    for (int j = 0; j < 32; j++) w[j] = wsrc[j];

    const int sidx = (layer * 2 + dir) * 256;
    h_buf[0][tid] = (group == 0) ? h0[sidx + tid] : 0.f;
    float creg = 0.f;
    if (tid < 32) creg = (group == 0) ? c0[sidx + (int)rank * 32 + tid] : 0.f;

    unsigned mb0 = smem_u32(&mbar[0]);
    unsigned mb1 = smem_u32(&mbar[1]);
    if (tid == 0) {
        mbar_init(mb0, 1);
        mbar_init(mb1, 1);
        mbar_arm(mb1, 1024);
        mbar_arm(mb0, 1024);
    }
    __syncthreads();
    cluster_sync_();

    const int xcol = dir * 1024 + grow;
    const int ycol = dir * 256 + unit;
    const long mbase = (long)group * 32 * 128;
    unsigned ph0 = 0, ph1 = 0;

    auto midx = [&](int q) -> long {
        int t = q & 127;
        if (dir) t = 127 - t;
        return mbase + (q & ~127) + t;
    };

    float xcur = (tid < 128) ? __ldg(gx + midx(0) * GXN + xcol) : 0.f;

    for (int q = 0; q < 4096; q++) {
        const int p = q & 1;

        float xnext = 0.f;
        if (tid < 128 && q + 1 < 4096)
            xnext = __ldg(gx + midx(q + 1) * GXN + xcol);

        if (q > 0) {
            if (p) { mbar_wait(mb1, ph1); ph1 ^= 1; }
            else   { mbar_wait(mb0, ph0); ph0 ^= 1; }
            if (tid == 1) mbar_arm(p ? mb1 : mb0, 1024);
        }

        const ulonglong2* hb = ((const ulonglong2*)h_buf[p]) + half * 32;
        ull acc0 = 0, acc1 = 0;
#pragma unroll
        for (int j = 0; j < 32; j++) {
            ulonglong2 hv = hb[j];
            fma2(acc0, hv.x, w[j].x);
            fma2(acc1, hv.y, w[j].y);
        }
        float s = sum2(acc0) + sum2(acc1);
        partial[tid] = (tid < 128) ? (s + xcur) : s;
        __syncthreads();

        if (tid < 32) {
            float iv = partial[tid]      + partial[tid + 128];
            float fv = partial[tid + 32] + partial[tid + 160];
            float gv = partial[tid + 64] + partial[tid + 192];
            float ov = partial[tid + 96] + partial[tid + 224];
            float ig = sigmoid_fast(iv);
            float fg = sigmoid_fast(fv);
            float og = sigmoid_fast(ov);
            float gg = tanh_fast(gv);
            creg = fmaf(fg, creg, ig * gg);
            float h = og * tanh_fast(creg);
            y[midx(q) * Hn + ycol] = h;

            const int pn = p ^ 1;
            unsigned ldst = smem_u32(&h_buf[pn][unit]);
            unsigned lbar = pn ? mb1 : mb0;
#pragma unroll
            for (unsigned r = 0; r < 8; r++)
                st_async_f32(mapa_cluster(ldst, r), h, mapa_cluster(lbar, r));
        }
        xcur = xnext;
    }

    mbar_wait(mb0, ph0);
    cluster_sync_();
}

// ---------------------------------------------------------------------------
// 5) max over batch axis
// ---------------------------------------------------------------------------
__global__ void maxpool_kernel(const float* __restrict__ y1, float* __restrict__ out2)
{
    int idx = blockIdx.x * 256 + threadIdx.x;    // 0..65535
    int s = idx >> 9, h = idx & 511;
    float mx = -3.402823466e38f;
    for (int b = 0; b < 128; b++) {
        float v = y1[((long)b * 128 + s) * Hn + h];
        mx = fmaxf(mx, v);
    }
    out2[idx] = mx;
}

// ---------------------------------------------------------------------------
extern "C" void kernel_launch(void* const* d_in, const int* in_sizes, int n_in,
                              void* d_out, int out_size)
{
    const int*   rt  = (const int*)d_in[0];
    const int*   re  = (const int*)d_in[1];
    const int*   rm  = (const int*)d_in[2];
    const float* h0  = (const float*)d_in[3];
    const float* c0  = (const float*)d_in[4];
    const float* Ert = (const float*)d_in[5];
    const float* Ere = (const float*)d_in[6];
    const float* Erm = (const float*)d_in[7];
    const float* Wih = (const float*)d_in[8];   // (2,2,1024,512)
    const float* Whh = (const float*)d_in[9];   // (2,2,1024,256)
    const float* bih = (const float*)d_in[10];  // (2,2,1024)
    const float* bhh = (const float*)d_in[11];

    float* out  = (float*)d_out;
    float* y1   = out;                       // bilstm_outs (128,128,512)
    float* out2 = out + (long)Bn * Sn * Hn;  // output (128,512)

    void *p_x = nullptr, *p_y0 = nullptr, *p_a2 = nullptr, *p_w2 = nullptr;
    cudaGetSymbolAddress(&p_x,  g_x);
    cudaGetSymbolAddress(&p_y0, g_y0);
    cudaGetSymbolAddress(&p_a2, g_a2);
    cudaGetSymbolAddress(&p_w2, g_w2);
    float* gx = (float*)p_x;
    float* y0 = (float*)p_y0;
    __nv_bfloat16* a2 = (__nv_bfloat16*)p_a2;
    __nv_bfloat16* w2 = (__nv_bfloat16*)p_w2;

    cudaFuncSetAttribute(gemm_mma_kernel,
                         cudaFuncAttributeMaxDynamicSharedMemorySize, GEMM_SMEM);

    dim3 ggrid(GXN / 128, NROW / 128);   // (16, 128)

    // layer 0
    embed_split_kernel<<<NROW, 128>>>(rt, re, rm, Ert, Ere, Erm);
    w_split_kernel<<<dim3(2048, 2), 128>>>(Wih);
    gemm_mma_kernel<<<ggrid, 256, GEMM_SMEM>>>(a2, w2, bih, bhh, gx);
    lstm_layer_kernel<<<64, 256>>>(Whh, gx, y0, h0, c0, 0);

    // layer 1
    y_split_kernel<<<NROW, 128>>>(y0);
    gemm_mma_kernel<<<ggrid, 256, GEMM_SMEM>>>(
        a2, w2 + (long)2048 * KSPL, bih + 2048, bhh + 2048, gx);
    lstm_layer_kernel<<<64, 256>>>(Whh, gx, y1, h0, c0, 1);

    maxpool_kernel<<<256, 256>>>(y1, out2);
}